// round 3
// baseline (speedup 1.0000x reference)
#include <cuda_runtime.h>
#include <cuda_fp16.h>

#define B_   4
#define CIN  256
#define CO_  64
#define N_   576   // 24*24
#define CV_  256

// Scratch (device globals — no allocation allowed)
__device__ float g_kp[B_ * N_ * CO_];          // (B, Nk, CO)
__device__ float g_qp[B_ * N_ * CO_];          // (B, Nq, CO)
__device__ float g_attn[B_ * N_ * N_];         // (B, Nk, Nq)

// ---------- packed helpers ----------
__device__ __forceinline__ unsigned long long pack2(float lo, float hi) {
    unsigned long long r;
    asm("mov.b64 %0, {%1, %2};" : "=l"(r) : "f"(lo), "f"(hi));
    return r;
}
__device__ __forceinline__ void unpack2(unsigned long long v, float& lo, float& hi) {
    asm("mov.b64 {%0, %1}, %2;" : "=f"(lo), "=f"(hi) : "l"(v));
}
__device__ __forceinline__ unsigned long long ffma2(unsigned long long a,
                                                    unsigned long long b,
                                                    unsigned long long c) {
    unsigned long long d;
    asm("fma.rn.f32x2 %0, %1, %2, %3;" : "=l"(d) : "l"(a), "l"(b), "l"(c));
    return d;
}
__device__ __forceinline__ float tanhfast(float x) {
    float y;
    asm("tanh.approx.f32 %0, %1;" : "=f"(y) : "f"(x));
    return y;
}
__device__ __forceinline__ unsigned tanh_h2(unsigned x) {
    unsigned y;
    asm("tanh.approx.f16x2 %0, %1;" : "=r"(y) : "r"(x));
    return y;
}
__device__ __forceinline__ __half2 u2h(unsigned u) { return *(__half2*)&u; }
__device__ __forceinline__ unsigned h2u(__half2 h) { return *(unsigned*)&h; }

// ============================================================================
// Kernel A: projections. out[b,n,c] = sum_ch X[b,ch,n]*W[c,ch] + bias[c]
// grid (36 n-tiles of 16, B, 2), 256 thr. Thread = 1c x 4n.
// X read via LDG.128 warp-broadcast (each element read once chip-wide, L2/DRAM
// streaming); W staged in smem (2 chunks of 128 ch).
// ============================================================================
__global__ void __launch_bounds__(256) proj_kernel(
    const float* __restrict__ key, const float* __restrict__ query,
    const float* __restrict__ Wk,  const float* __restrict__ bk,
    const float* __restrict__ Wq,  const float* __restrict__ bq)
{
    const int kind = blockIdx.z;
    const float* X    = kind ? query : key;    // (B, CIN, N)
    const float* W    = kind ? Wq    : Wk;     // (CO, CIN)
    const float* bias = kind ? bq    : bk;
    float* outp       = kind ? g_qp  : g_kp;   // (B, N, CO)

    const int b  = blockIdx.y;
    const int n0 = blockIdx.x * 16;

    __shared__ float sW[64][129];   // [c][ch-chunk], odd stride -> CF

    const int t  = threadIdx.x;
    const int c  = t & 63;
    const int ng = t >> 6;                        // 0..3, constant per warp pair
    const float* Xp = X + ((size_t)b * CIN) * N_ + n0 + ng * 4;

    unsigned long long acc0 = 0ull, acc1 = 0ull;

    #pragma unroll
    for (int ch0 = 0; ch0 < CIN; ch0 += 128) {
        // stage W chunk: 64 c x 128 ch (coalesced LDG, CF STS)
        #pragma unroll
        for (int i = t; i < 64 * 128; i += 256)
            sW[i >> 7][i & 127] = W[(i >> 7) * CIN + ch0 + (i & 127)];
        __syncthreads();

        const float* Xc = Xp + (size_t)ch0 * N_;
        #pragma unroll 8
        for (int ch = 0; ch < 128; ch++) {
            const float4 x4 = __ldg((const float4*)(Xc + (size_t)ch * N_));
            const float w = sW[c][ch];
            const unsigned long long ww = pack2(w, w);
            acc0 = ffma2(pack2(x4.x, x4.y), ww, acc0);
            acc1 = ffma2(pack2(x4.z, x4.w), ww, acc1);
        }
        __syncthreads();
    }

    const float bv = bias[c];
    float o0, o1, o2, o3;
    unpack2(acc0, o0, o1);
    unpack2(acc1, o2, o3);
    const int n = n0 + ng * 4;
    outp[((size_t)b * N_ + n + 0) * CO_ + c] = o0 + bv;   // coalesced over c
    outp[((size_t)b * N_ + n + 1) * CO_ + c] = o1 + bv;
    outp[((size_t)b * N_ + n + 2) * CO_ + c] = o2 + bv;
    outp[((size_t)b * N_ + n + 3) * CO_ + c] = o3 + bv;
}

// ============================================================================
// Kernel B: attn[b,k,q] = sigmoid( bf + sum_c tanh(kp[k,c]+qp[q,c])*wf[c] )
// grid (18 q-tiles, 18 k-tiles, B), 256 thr. Thread = 4k x 1q (q = lane).
// Tiles converted to half2 ONCE at smem load; inner loop is pure
// HADD2 + tanh.f16x2 + HFMA2 (no cvt on the hot path). fp32 combine at end.
// ============================================================================
__global__ void __launch_bounds__(256) attn_kernel(
    const float* __restrict__ wf, const float* __restrict__ bfp)
{
    const int b  = blockIdx.z;
    const int k0 = blockIdx.y * 32;
    const int q0 = blockIdx.x * 32;

    __shared__ unsigned skh[32][34];   // half2 pairs over c; stride 34 (8B rows)
    __shared__ unsigned sqh[32][34];
    __shared__ unsigned swh[32];

    const int t = threadIdx.x;
    #pragma unroll
    for (int j = 0; j < 4; j++) {
        const int idx = t + j * 256;       // 1024 half2 per tile
        const int r  = idx >> 5;
        const int cc = idx & 31;
        const float2 kv = *(const float2*)&g_kp[((size_t)b * N_ + k0 + r) * CO_ + cc * 2];
        const float2 qv = *(const float2*)&g_qp[((size_t)b * N_ + q0 + r) * CO_ + cc * 2];
        skh[r][cc] = h2u(__floats2half2_rn(kv.x, kv.y));
        sqh[r][cc] = h2u(__floats2half2_rn(qv.x, qv.y));
    }
    if (t < 32) {
        const float2 w = *(const float2*)&wf[t * 2];
        swh[t] = h2u(__floats2half2_rn(w.x, w.y));
    }
    __syncthreads();

    const int q  = t & 31;            // lane -> CF q loads, coalesced STG
    const int k4 = (t >> 5) * 4;      // 4 k's per thread (warp-constant -> bcast)

    __half2 ae[4], ao[4];
    #pragma unroll
    for (int i = 0; i < 4; i++) { ae[i] = __float2half2_rn(0.f); ao[i] = ae[i]; }

    const unsigned* __restrict__ qrow = sqh[q];

    #pragma unroll
    for (int cc = 0; cc < 32; cc += 2) {
        const uint2 qv = *(const uint2*)&qrow[cc];
        const uint2 wv = *(const uint2*)&swh[cc];
        #pragma unroll
        for (int i = 0; i < 4; i++) {
            const uint2 kv = *(const uint2*)&skh[k4 + i][cc];
            const unsigned t0 = tanh_h2(h2u(__hadd2(u2h(kv.x), u2h(qv.x))));
            const unsigned t1 = tanh_h2(h2u(__hadd2(u2h(kv.y), u2h(qv.y))));
            ae[i] = __hfma2(u2h(t0), u2h(wv.x), ae[i]);
            ao[i] = __hfma2(u2h(t1), u2h(wv.y), ao[i]);
        }
    }

    const float bf = __ldg(bfp);
    #pragma unroll
    for (int i = 0; i < 4; i++) {
        const float2 fe = __half22float2(ae[i]);
        const float2 fo = __half22float2(ao[i]);
        const float s = bf + ((fe.x + fe.y) + (fo.x + fo.y));
        g_attn[((size_t)b * N_ + k0 + k4 + i) * N_ + q0 + q] =
            fmaf(0.5f, tanhfast(0.5f * s), 0.5f);   // sigmoid
    }
}

// ============================================================================
// Kernel C: out[b,c,q] = sum_k value[b,c,k] * attn[b,k,q]
// grid (9 q-tiles of 64, 4 c-tiles of 64, B), 256 thr; thread = 4c x 4q.
// Per kk: 2x LDS.128 + 4 dup-movs + 8 FFMA2 -> issue stays under FMA floor.
// ============================================================================
__global__ void __launch_bounds__(256) out_kernel(
    const float* __restrict__ value, float* __restrict__ out)
{
    const int b  = blockIdx.z;
    const int c0 = blockIdx.y * 64;
    const int q0 = blockIdx.x * 64;

    __shared__ __align__(16) float sV[32][68];   // [k][c], 272B rows (16B-mult)
    __shared__ __align__(16) float sA[32][68];   // [k][q]

    const int t  = threadIdx.x;
    const int qg = t & 15;          // q = qg*4 .. +3
    const int cg = t >> 4;          // c = cg*4 .. +3

    unsigned long long acc[4][2];
    #pragma unroll
    for (int i = 0; i < 4; i++) { acc[i][0] = 0ull; acc[i][1] = 0ull; }

    for (int k0 = 0; k0 < N_; k0 += 32) {
        {   // V tile 64c x 32k, transpose into sV[k][c] (coalesced LDG over k)
            const int kk = t & 31;
            const int cb = t >> 5;
            #pragma unroll
            for (int i = 0; i < 8; i++) {
                const int cr = cb + i * 8;
                sV[kk][cr] = value[((size_t)(b * CV_ + c0 + cr)) * N_ + k0 + kk];
            }
        }
        {   // A tile 32k x 64q (coalesced LDG over q, CF STS)
            const int q  = t & 63;
            const int kb = t >> 6;
            #pragma unroll
            for (int i = 0; i < 8; i++) {
                const int kr = kb + i * 4;
                sA[kr][q] = g_attn[((size_t)b * N_ + k0 + kr) * N_ + q0 + q];
            }
        }
        __syncthreads();

        #pragma unroll 8
        for (int kk = 0; kk < 32; kk++) {
            const float4 v4 = *(const float4*)&sV[kk][cg * 4];        // 4 c
            const ulonglong2 a2 = *(const ulonglong2*)&sA[kk][qg * 4]; // 4 q
            const unsigned long long v0 = pack2(v4.x, v4.x);
            const unsigned long long v1 = pack2(v4.y, v4.y);
            const unsigned long long v2 = pack2(v4.z, v4.z);
            const unsigned long long v3 = pack2(v4.w, v4.w);
            acc[0][0] = ffma2(v0, a2.x, acc[0][0]);
            acc[0][1] = ffma2(v0, a2.y, acc[0][1]);
            acc[1][0] = ffma2(v1, a2.x, acc[1][0]);
            acc[1][1] = ffma2(v1, a2.y, acc[1][1]);
            acc[2][0] = ffma2(v2, a2.x, acc[2][0]);
            acc[2][1] = ffma2(v2, a2.y, acc[2][1]);
            acc[3][0] = ffma2(v3, a2.x, acc[3][0]);
            acc[3][1] = ffma2(v3, a2.y, acc[3][1]);
        }
        __syncthreads();
    }

    #pragma unroll
    for (int i = 0; i < 4; i++) {
        float o0, o1, o2, o3;
        unpack2(acc[i][0], o0, o1);
        unpack2(acc[i][1], o2, o3);
        *(float4*)&out[((size_t)(b * CV_ + c0 + cg * 4 + i)) * N_ + q0 + qg * 4] =
            make_float4(o0, o1, o2, o3);
    }
}

// ============================================================================
extern "C" void kernel_launch(void* const* d_in, const int* in_sizes, int n_in,
                              void* d_out, int out_size)
{
    const float* key   = (const float*)d_in[0];
    const float* query = (const float*)d_in[1];
    const float* value = (const float*)d_in[2];
    const float* Wk    = (const float*)d_in[3];
    const float* bk    = (const float*)d_in[4];
    const float* Wq    = (const float*)d_in[5];
    const float* bq    = (const float*)d_in[6];
    const float* wf    = (const float*)d_in[7];
    const float* bf    = (const float*)d_in[8];
    float* out = (float*)d_out;

    proj_kernel<<<dim3(N_ / 16, B_, 2), 256>>>(key, query, Wk, bk, Wq, bq);
    attn_kernel<<<dim3(N_ / 32, N_ / 32, B_), 256>>>(wf, bf);
    out_kernel<<<dim3(N_ / 64, CV_ / 64, B_), 256>>>(value, out);
}